// round 7
// baseline (speedup 1.0000x reference)
#include <cuda_runtime.h>
#include <cuda_fp16.h>

// Dims fixed by the reference: x is (B=8, T=2048, F=128) float32.
#define BB 8
#define TT 2048
#define FF 128
#define NN (BB * TT * FF)           // 2,097,152
#define SB (TT * FF)                // 262144
#define ST (FF)                     // 128

#define TAU_F (1.0f / 6.0f)
#define NPAIR 14                    // 14 double-steps = updates #2..#29

#define T2 4                        // output T-rows per block
#define NW2 16
#define NT2 (NW2 * 32)              // 512 threads
#define F4 (FF / 4)                 // 32 float4 per row == one warp

// smem layout: s_p (3 comps x 8 rows x 8 b x 32 f4, fp16x4=uint2) then s_out.
#define SP_ELEMS (3 * 8 * BB * F4)          // uint2 count
#define SP_BYTES (SP_ELEMS * 8)             // 49152
#define SO_BYTES (7 * BB * F4 * 16)         // 28672
#define SM_BYTES (SP_BYTES + SO_BYTES)      // 77824

// Ping-pong dual buffers in fp16 (math stays fp32).
__device__ __half g_pa0[NN], g_pa1[NN], g_pa2[NN];
__device__ __half g_pb0[NN], g_pb1[NN], g_pb2[NN];

__device__ __forceinline__ float4 ld4(const float* __restrict__ p, int idx) {
    return *reinterpret_cast<const float4*>(p + idx);
}
__device__ __forceinline__ void st4(float* __restrict__ p, int idx, float4 v) {
    *reinterpret_cast<float4*>(p + idx) = v;
}
__device__ __forceinline__ float4 u2tof4(uint2 u) {
    __half2 h0 = *reinterpret_cast<__half2*>(&u.x);
    __half2 h1 = *reinterpret_cast<__half2*>(&u.y);
    float2 f0 = __half22float2(h0);
    float2 f1 = __half22float2(h1);
    return make_float4(f0.x, f0.y, f1.x, f1.y);
}
__device__ __forceinline__ uint2 f4tou2(float4 v) {
    __half2 h0 = __floats2half2_rn(v.x, v.y);
    __half2 h1 = __floats2half2_rn(v.z, v.w);
    uint2 u;
    u.x = *reinterpret_cast<unsigned*>(&h0);
    u.y = *reinterpret_cast<unsigned*>(&h1);
    return u;
}
__device__ __forceinline__ float4 ldh4(const __half* __restrict__ p, int idx) {
    return u2tof4(*reinterpret_cast<const uint2*>(p + idx));
}
__device__ __forceinline__ void sth4(__half* __restrict__ p, int idx, float4 v) {
    *reinterpret_cast<uint2*>(p + idx) = f4tou2(v);
}
__device__ __forceinline__ float4 f4sub(float4 a, float4 b) {
    return make_float4(a.x - b.x, a.y - b.y, a.z - b.z, a.w - b.w);
}
__device__ __forceinline__ float4 f4add(float4 a, float4 b) {
    return make_float4(a.x + b.x, a.y + b.y, a.z + b.z, a.w + b.w);
}

#define SPI(c, rp, b) ((((c) * 8 + (rp)) * BB + (b)) * F4)
#define SOI(ro, b)    (((ro) * BB + (b)) * F4)

// out = img + div(p) for one float4, p components already as float4.
// prev-w of a2 comes via shuffle (f-1 term).
__device__ __forceinline__ float4 divsite(float4 dimg, float4 a0, float4 a1,
                                          float4 a2, float4 pb0, float4 pt1,
                                          bool hasB, bool hasT, int lane) {
    float4 d = f4sub(f4sub(f4sub(dimg, a0), a1), a2);
    if (hasB) d = f4add(d, pb0);
    if (hasT) d = f4add(d, pt1);
    float prevw = __shfl_up_sync(0xffffffffu, a2.w, 1);
    if (lane > 0) d.x += prevw;
    d.y += a2.x; d.z += a2.y; d.w += a2.z;
    return d;
}

// ---------------------------------------------------------------------------
// k_first: p = 0 => out = img, g = grad(img). Writes pA (fp16).
// ---------------------------------------------------------------------------
__global__ __launch_bounds__(256)
void k_first(const float* __restrict__ img, const float* __restrict__ lam) {
    int tid = blockIdx.x * 256 + threadIdx.x;          // float4 index
    if (tid >= NN / 4) return;
    int lane = tid & 31;
    int t = (tid >> 5) & (TT - 1);
    int b = tid >> 16;
    int idx = tid * 4;

    float4 o = ld4(img, idx);
    float4 gb = make_float4(0, 0, 0, 0), gt = make_float4(0, 0, 0, 0), gf;
    if (b < BB - 1) gb = f4sub(ld4(img, idx + SB), o);
    if (t < TT - 1) gt = f4sub(ld4(img, idx + ST), o);
    float nx = __shfl_down_sync(0xffffffffu, o.x, 1);
    gf.x = o.y - o.x; gf.y = o.z - o.y; gf.z = o.w - o.z;
    gf.w = (lane < 31) ? (nx - o.w) : 0.0f;

    float tw = TAU_F / lam[0];
    float4 r0, r1, r2;
#define FIRST_UPD(c)                                                     \
    { float n = sqrtf(gb.c * gb.c + gt.c * gt.c + gf.c * gf.c);          \
      float inv = __fdividef(1.0f, n * tw + 1.0f);                       \
      r0.c = (-TAU_F * gb.c) * inv;                                      \
      r1.c = (-TAU_F * gt.c) * inv;                                      \
      r2.c = (-TAU_F * gf.c) * inv; }
    FIRST_UPD(x) FIRST_UPD(y) FIRST_UPD(z) FIRST_UPD(w)
#undef FIRST_UPD
    sth4(g_pa0, idx, r0);
    sth4(g_pa1, idx, r1);
    sth4(g_pa2, idx, r2);
}

// ---------------------------------------------------------------------------
// k_fused2: TWO Chambolle steps per launch.
// Tile = all 8 b x T2 output t-rows x full F. Halo recompute in T.
//   Phase L : load pIn rows [t0-2, t0+6) -> s_p (fp16)
//   Phase O0: out0 rows [t0-1, t0+6) -> s_out (fp32)
//   Phase P1: p1 rows [t0-1, t0+5) -> overwrite s_p in place (per-point safe)
//   Phase O1: out1 rows [t0, t0+5) -> s_out (reuse; out0 dead)
//   Phase P2: p2 rows [t0, t0+4) -> global p_out (fp16)
// Every cross-row read is predicated on global-T validity, so halo rows that
// were never loaded/computed are never read. All guards are row-uniform.
// ---------------------------------------------------------------------------
template <bool A2B>
__global__ __launch_bounds__(NT2, 2)
void k_fused2(const float* __restrict__ img, const float* __restrict__ lam) {
    const __half* __restrict__ q0 = A2B ? g_pa0 : g_pb0;
    const __half* __restrict__ q1 = A2B ? g_pa1 : g_pb1;
    const __half* __restrict__ q2 = A2B ? g_pa2 : g_pb2;
    __half* __restrict__ r0 = A2B ? g_pb0 : g_pa0;
    __half* __restrict__ r1 = A2B ? g_pb1 : g_pa1;
    __half* __restrict__ r2 = A2B ? g_pb2 : g_pa2;

    extern __shared__ char sm[];
    uint2* s_p = reinterpret_cast<uint2*>(sm);
    float4* s_o = reinterpret_cast<float4*>(sm + SP_BYTES);

    int warp = threadIdx.x >> 5;
    int lane = threadIdx.x & 31;                        // == f4
    int t0 = blockIdx.x * T2;
    float tw = TAU_F / lam[0];

    // Phase L: 8 rows x 8 b = 64 jobs
    for (int j = warp; j < 64; j += NW2) {
        int rp = j >> 3, b = j & 7;
        int t = t0 - 2 + rp;
        if (t >= 0 && t < TT) {
            int idx = b * SB + t * ST + lane * 4;
            s_p[SPI(0, rp, b) + lane] = *reinterpret_cast<const uint2*>(q0 + idx);
            s_p[SPI(1, rp, b) + lane] = *reinterpret_cast<const uint2*>(q1 + idx);
            s_p[SPI(2, rp, b) + lane] = *reinterpret_cast<const uint2*>(q2 + idx);
        }
    }
    __syncthreads();

    // Phase O0: 7 rows x 8 b = 56 jobs. ro -> t = t0-1+ro, rp = ro+1.
    for (int j = warp; j < 56; j += NW2) {
        int ro = j >> 3, b = j & 7;
        int t = t0 - 1 + ro, rp = ro + 1;
        if (t >= 0 && t < TT) {
            float4 a0 = u2tof4(s_p[SPI(0, rp, b) + lane]);
            float4 a1 = u2tof4(s_p[SPI(1, rp, b) + lane]);
            float4 a2 = u2tof4(s_p[SPI(2, rp, b) + lane]);
            float4 pb0 = (b > 0) ? u2tof4(s_p[SPI(0, rp, b - 1) + lane])
                                 : make_float4(0, 0, 0, 0);
            float4 pt1 = (t > 0) ? u2tof4(s_p[SPI(1, rp - 1, b) + lane])
                                 : make_float4(0, 0, 0, 0);
            float4 dimg = ld4(img, b * SB + t * ST + lane * 4);
            s_o[SOI(ro, b) + lane] =
                divsite(dimg, a0, a1, a2, pb0, pt1, b > 0, t > 0, lane);
        }
    }
    __syncthreads();

    // Phase P1: 6 rows x 8 b = 48 jobs. rw1 -> t = t0-1+rw1, rp = rw1+1,
    // out0 rows rw1 / rw1+1. Overwrites s_p[rp] in place (own-point reads only).
    for (int j = warp; j < 48; j += NW2) {
        int rw1 = j >> 3, b = j & 7;
        int t = t0 - 1 + rw1, rp = rw1 + 1;
        if (t >= 0 && t < TT) {
            float4 o = s_o[SOI(rw1, b) + lane];
            float4 gb = make_float4(0, 0, 0, 0), gt = make_float4(0, 0, 0, 0), gf;
            if (b < BB - 1) gb = f4sub(s_o[SOI(rw1, b + 1) + lane], o);
            if (t < TT - 1) gt = f4sub(s_o[SOI(rw1 + 1, b) + lane], o);
            float nx = __shfl_down_sync(0xffffffffu, o.x, 1);
            gf.x = o.y - o.x; gf.y = o.z - o.y; gf.z = o.w - o.z;
            gf.w = (lane < 31) ? (nx - o.w) : 0.0f;

            float4 a0 = u2tof4(s_p[SPI(0, rp, b) + lane]);
            float4 a1 = u2tof4(s_p[SPI(1, rp, b) + lane]);
            float4 a2 = u2tof4(s_p[SPI(2, rp, b) + lane]);
            float4 o0, o1, o2;
#define UPD(c)                                                            \
            { float n = sqrtf(gb.c * gb.c + gt.c * gt.c + gf.c * gf.c);   \
              float inv = __fdividef(1.0f, n * tw + 1.0f);                \
              o0.c = (a0.c - TAU_F * gb.c) * inv;                         \
              o1.c = (a1.c - TAU_F * gt.c) * inv;                         \
              o2.c = (a2.c - TAU_F * gf.c) * inv; }
            UPD(x) UPD(y) UPD(z) UPD(w)
#undef UPD
            s_p[SPI(0, rp, b) + lane] = f4tou2(o0);
            s_p[SPI(1, rp, b) + lane] = f4tou2(o1);
            s_p[SPI(2, rp, b) + lane] = f4tou2(o2);
        }
    }
    __syncthreads();

    // Phase O1: 5 rows x 8 b = 40 jobs. ro1 -> t = t0+ro1, p1 at rp = ro1+2.
    for (int j = warp; j < 40; j += NW2) {
        int ro1 = j >> 3, b = j & 7;
        int t = t0 + ro1, rp = ro1 + 2;
        if (t < TT) {
            float4 a0 = u2tof4(s_p[SPI(0, rp, b) + lane]);
            float4 a1 = u2tof4(s_p[SPI(1, rp, b) + lane]);
            float4 a2 = u2tof4(s_p[SPI(2, rp, b) + lane]);
            float4 pb0 = (b > 0) ? u2tof4(s_p[SPI(0, rp, b - 1) + lane])
                                 : make_float4(0, 0, 0, 0);
            float4 pt1 = (t > 0) ? u2tof4(s_p[SPI(1, rp - 1, b) + lane])
                                 : make_float4(0, 0, 0, 0);
            float4 dimg = ld4(img, b * SB + t * ST + lane * 4);
            s_o[SOI(ro1, b) + lane] =
                divsite(dimg, a0, a1, a2, pb0, pt1, b > 0, t > 0, lane);
        }
    }
    __syncthreads();

    // Phase P2: 4 rows x 8 b = 32 jobs. rw2 -> t = t0+rw2, p1 at rp = rw2+2.
    for (int j = warp; j < 32; j += NW2) {
        int rw2 = j >> 3, b = j & 7;
        int t = t0 + rw2, rp = rw2 + 2;
        int idx = b * SB + t * ST + lane * 4;

        float4 o = s_o[SOI(rw2, b) + lane];
        float4 gb = make_float4(0, 0, 0, 0), gt = make_float4(0, 0, 0, 0), gf;
        if (b < BB - 1) gb = f4sub(s_o[SOI(rw2, b + 1) + lane], o);
        if (t < TT - 1) gt = f4sub(s_o[SOI(rw2 + 1, b) + lane], o);
        float nx = __shfl_down_sync(0xffffffffu, o.x, 1);
        gf.x = o.y - o.x; gf.y = o.z - o.y; gf.z = o.w - o.z;
        gf.w = (lane < 31) ? (nx - o.w) : 0.0f;

        float4 a0 = u2tof4(s_p[SPI(0, rp, b) + lane]);
        float4 a1 = u2tof4(s_p[SPI(1, rp, b) + lane]);
        float4 a2 = u2tof4(s_p[SPI(2, rp, b) + lane]);
        float4 o0, o1, o2;
#define UPD(c)                                                            \
        { float n = sqrtf(gb.c * gb.c + gt.c * gt.c + gf.c * gf.c);       \
          float inv = __fdividef(1.0f, n * tw + 1.0f);                    \
          o0.c = (a0.c - TAU_F * gb.c) * inv;                             \
          o1.c = (a1.c - TAU_F * gt.c) * inv;                             \
          o2.c = (a2.c - TAU_F * gf.c) * inv; }
        UPD(x) UPD(y) UPD(z) UPD(w)
#undef UPD
        sth4(r0, idx, o0);
        sth4(r1, idx, o1);
        sth4(r2, idx, o2);
    }
}

// ---------------------------------------------------------------------------
// k_final: out = img + div(pA) + bias[f].
// ---------------------------------------------------------------------------
__global__ __launch_bounds__(256)
void k_final(const float* __restrict__ img, const float* __restrict__ bias,
             float* __restrict__ out) {
    int tid = blockIdx.x * 256 + threadIdx.x;
    if (tid >= NN / 4) return;
    int lane = tid & 31;
    int t = (tid >> 5) & (TT - 1);
    int b = tid >> 16;
    int idx = tid * 4;

    float4 d = ld4(img, idx);
    float4 a0 = ldh4(g_pa0, idx);
    float4 a1 = ldh4(g_pa1, idx);
    float4 a2 = ldh4(g_pa2, idx);
    d = f4sub(f4sub(f4sub(d, a0), a1), a2);
    if (b > 0) d = f4add(d, ldh4(g_pa0, idx - SB));
    if (t > 0) d = f4add(d, ldh4(g_pa1, idx - ST));
    float prevw = __shfl_up_sync(0xffffffffu, a2.w, 1);
    if (lane > 0) d.x += prevw;
    d.y += a2.x; d.z += a2.y; d.w += a2.z;

    d = f4add(d, ld4(bias, lane * 4));
    st4(out, idx, d);
}

extern "C" void kernel_launch(void* const* d_in, const int* in_sizes, int n_in,
                              void* d_out, int out_size) {
    const float* x   = (const float*)d_in[0];   // (8, 2048, 128)
    const float* lam = (const float*)d_in[1];   // (1, 1)
    const float* b   = (const float*)d_in[2];   // (1, 1, 128)
    float* out = (float*)d_out;

    const int vblocks = (NN / 4 + 255) / 256;   // 2048
    const int f2blocks = TT / T2;               // 512

    // Raise the dynamic-smem cap (77,824 B > 48 KB default). Host-side
    // attribute set, not a stream op — graph-capture safe, deterministic.
    cudaFuncSetAttribute(k_fused2<true>,
                         cudaFuncAttributeMaxDynamicSharedMemorySize, SM_BYTES);
    cudaFuncSetAttribute(k_fused2<false>,
                         cudaFuncAttributeMaxDynamicSharedMemorySize, SM_BYTES);

    // Update #1 (p = 0): write pA directly from img.
    k_first<<<vblocks, 256>>>(x, lam);

    // Updates #2..#29 as 14 double-steps, ping-pong A <-> B (even -> ends in A).
    for (int it = 0; it < NPAIR; ++it) {
        if ((it & 1) == 0)
            k_fused2<true><<<f2blocks, NT2, SM_BYTES>>>(x, lam);   // A -> B
        else
            k_fused2<false><<<f2blocks, NT2, SM_BYTES>>>(x, lam);  // B -> A
    }

    k_final<<<vblocks, 256>>>(x, b, out);
}

// round 8
// speedup vs baseline: 1.2053x; 1.2053x over previous
#include <cuda_runtime.h>
#include <cuda_fp16.h>

// Dims fixed by the reference: x is (B=8, T=2048, F=128) float32.
#define BB 8
#define TT 2048
#define FF 128
#define NN (BB * TT * FF)           // 2,097,152
#define SB (TT * FF)                // 262144
#define ST (FF)                     // 128

#define TAU_F (1.0f / 6.0f)
#define NFUSED 28                   // updates #2..#29 (update #1 is k_first)

#define TTILE 2                     // T-rows per block tile (grid = 1024)
#define NWARP 8
#define NTHREADS (NWARP * 32)       // 256
#define F4 (FF / 4)                 // 32 float4/half4 per row == one warp

// Ping-pong dual buffers in fp16 (math stays fp32). No runtime allocation.
__device__ __half g_pa0[NN], g_pa1[NN], g_pa2[NN];
__device__ __half g_pb0[NN], g_pb1[NN], g_pb2[NN];

__device__ __forceinline__ float4 ld4(const float* __restrict__ p, int idx) {
    return *reinterpret_cast<const float4*>(p + idx);
}
__device__ __forceinline__ void st4(float* __restrict__ p, int idx, float4 v) {
    *reinterpret_cast<float4*>(p + idx) = v;
}
// 8-byte vector load of 4 halves -> float4
__device__ __forceinline__ float4 ldh4(const __half* __restrict__ p, int idx) {
    uint2 u = *reinterpret_cast<const uint2*>(p + idx);
    __half2 h0 = *reinterpret_cast<__half2*>(&u.x);
    __half2 h1 = *reinterpret_cast<__half2*>(&u.y);
    float2 f0 = __half22float2(h0);
    float2 f1 = __half22float2(h1);
    return make_float4(f0.x, f0.y, f1.x, f1.y);
}
__device__ __forceinline__ void sth4(__half* __restrict__ p, int idx, float4 v) {
    __half2 h0 = __floats2half2_rn(v.x, v.y);
    __half2 h1 = __floats2half2_rn(v.z, v.w);
    uint2 u;
    u.x = *reinterpret_cast<unsigned*>(&h0);
    u.y = *reinterpret_cast<unsigned*>(&h1);
    *reinterpret_cast<uint2*>(p + idx) = u;
}
__device__ __forceinline__ float4 f4sub(float4 a, float4 b) {
    return make_float4(a.x - b.x, a.y - b.y, a.z - b.z, a.w - b.w);
}
__device__ __forceinline__ float4 f4add(float4 a, float4 b) {
    return make_float4(a.x + b.x, a.y + b.y, a.z + b.z, a.w + b.w);
}

// ---------------------------------------------------------------------------
// k_first: p = 0  =>  out = img, g = grad(img). Writes pA (fp16).
// ---------------------------------------------------------------------------
__global__ __launch_bounds__(NTHREADS)
void k_first(const float* __restrict__ img, const float* __restrict__ lam) {
    int tid = blockIdx.x * blockDim.x + threadIdx.x;   // float4 index
    if (tid >= NN / 4) return;
    int lane = tid & 31;                               // == f4
    int t = (tid >> 5) & (TT - 1);
    int b = tid >> 16;
    int idx = tid * 4;

    float4 o = ld4(img, idx);
    float4 gb = make_float4(0, 0, 0, 0), gt = make_float4(0, 0, 0, 0), gf;
    if (b < BB - 1) gb = f4sub(ld4(img, idx + SB), o);
    if (t < TT - 1) gt = f4sub(ld4(img, idx + ST), o);
    float nx = __shfl_down_sync(0xffffffffu, o.x, 1);
    gf.x = o.y - o.x; gf.y = o.z - o.y; gf.z = o.w - o.z;
    gf.w = (lane < 31) ? (nx - o.w) : 0.0f;            // f==127 boundary

    float tw = TAU_F / lam[0];
    float4 r0, r1, r2;
#define FIRST_UPD(c)                                                     \
    { float n = sqrtf(gb.c * gb.c + gt.c * gt.c + gf.c * gf.c);          \
      float inv = __fdividef(1.0f, n * tw + 1.0f);                       \
      r0.c = (-TAU_F * gb.c) * inv;                                      \
      r1.c = (-TAU_F * gt.c) * inv;                                      \
      r2.c = (-TAU_F * gf.c) * inv; }
    FIRST_UPD(x) FIRST_UPD(y) FIRST_UPD(z) FIRST_UPD(w)
#undef FIRST_UPD
    sth4(g_pa0, idx, r0);
    sth4(g_pa1, idx, r1);
    sth4(g_pa2, idx, r2);
}

// ---------------------------------------------------------------------------
// k_fused: one Chambolle step. Block tile = (all 8 b) x (TTILE t-rows) x (F).
// Phase A: out = img + div(p_in) into smem (fp32) for TTILE+1 t-rows.
// Phase B: gradients from smem, update p_out (fp16). Ping-pong p buffers.
// TTILE=2 -> grid 1024 for occupancy (R5's TTILE=4 was grid-limited at 39%).
// ---------------------------------------------------------------------------
template <bool A2B>
__global__ __launch_bounds__(NTHREADS)
void k_fused(const float* __restrict__ img, const float* __restrict__ lam) {
    const __half* __restrict__ q0 = A2B ? g_pa0 : g_pb0;
    const __half* __restrict__ q1 = A2B ? g_pa1 : g_pb1;
    const __half* __restrict__ q2 = A2B ? g_pa2 : g_pb2;
    __half* __restrict__ r0 = A2B ? g_pb0 : g_pa0;
    __half* __restrict__ r1 = A2B ? g_pb1 : g_pa1;
    __half* __restrict__ r2 = A2B ? g_pb2 : g_pa2;

    __shared__ float4 s_out[BB][TTILE + 1][F4];        // 8*3*32*16 = 12 KB

    int warp = threadIdx.x >> 5;
    int lane = threadIdx.x & 31;                        // == f4
    int t0 = blockIdx.x * TTILE;
    float tw = TAU_F / lam[0];

    // Phase A: 8*(TTILE+1) = 24 rows over 8 warps (3 each). Guards row-uniform.
    for (int r = warp; r < BB * (TTILE + 1); r += NWARP) {
        int b = r / (TTILE + 1);
        int trow = r - b * (TTILE + 1);
        int t = t0 + trow;
        if (t < TT) {
            int idx = b * SB + t * ST + lane * 4;
            float4 d = ld4(img, idx);
            float4 a0 = ldh4(q0, idx);
            float4 a1 = ldh4(q1, idx);
            float4 a2 = ldh4(q2, idx);
            d = f4sub(f4sub(f4sub(d, a0), a1), a2);
            if (b > 0) d = f4add(d, ldh4(q0, idx - SB));
            if (t > 0) d = f4add(d, ldh4(q1, idx - ST));
            // + p2[f-1]: within-vector for y,z,w; lane-1's .w for x (0 at f==0)
            float prevw = __shfl_up_sync(0xffffffffu, a2.w, 1);
            if (lane > 0) d.x += prevw;
            d.y += a2.x; d.z += a2.y; d.w += a2.z;
            s_out[b][trow][lane] = d;
        }
    }
    __syncthreads();

    // Phase B: 8*TTILE = 16 rows over 8 warps (2 each).
    for (int r = warp; r < BB * TTILE; r += NWARP) {
        int b = r >> 1;                                 // r / TTILE
        int trow = r & (TTILE - 1);
        int t = t0 + trow;
        int idx = b * SB + t * ST + lane * 4;

        float4 o = s_out[b][trow][lane];
        float4 gb = make_float4(0, 0, 0, 0), gt = make_float4(0, 0, 0, 0), gf;
        if (b < BB - 1) gb = f4sub(s_out[b + 1][trow][lane], o);
        if (t < TT - 1) gt = f4sub(s_out[b][trow + 1][lane], o);
        float nx = __shfl_down_sync(0xffffffffu, o.x, 1);
        gf.x = o.y - o.x; gf.y = o.z - o.y; gf.z = o.w - o.z;
        gf.w = (lane < 31) ? (nx - o.w) : 0.0f;

        float4 a0 = ldh4(q0, idx);
        float4 a1 = ldh4(q1, idx);
        float4 a2 = ldh4(q2, idx);
        float4 o0, o1, o2;
#define UPD(c)                                                            \
        { float n = sqrtf(gb.c * gb.c + gt.c * gt.c + gf.c * gf.c);       \
          float inv = __fdividef(1.0f, n * tw + 1.0f);                    \
          o0.c = (a0.c - TAU_F * gb.c) * inv;                             \
          o1.c = (a1.c - TAU_F * gt.c) * inv;                             \
          o2.c = (a2.c - TAU_F * gf.c) * inv; }
        UPD(x) UPD(y) UPD(z) UPD(w)
#undef UPD
        sth4(r0, idx, o0);
        sth4(r1, idx, o1);
        sth4(r2, idx, o2);
    }
}

// ---------------------------------------------------------------------------
// k_final: out = img + div(pA) + bias[f]. One float4/thread.
// ---------------------------------------------------------------------------
__global__ __launch_bounds__(NTHREADS)
void k_final(const float* __restrict__ img, const float* __restrict__ bias,
             float* __restrict__ out) {
    int tid = blockIdx.x * blockDim.x + threadIdx.x;
    if (tid >= NN / 4) return;
    int lane = tid & 31;                               // == f4
    int t = (tid >> 5) & (TT - 1);
    int b = tid >> 16;
    int idx = tid * 4;

    float4 d = ld4(img, idx);
    float4 a0 = ldh4(g_pa0, idx);
    float4 a1 = ldh4(g_pa1, idx);
    float4 a2 = ldh4(g_pa2, idx);
    d = f4sub(f4sub(f4sub(d, a0), a1), a2);
    if (b > 0) d = f4add(d, ldh4(g_pa0, idx - SB));
    if (t > 0) d = f4add(d, ldh4(g_pa1, idx - ST));
    float prevw = __shfl_up_sync(0xffffffffu, a2.w, 1);
    if (lane > 0) d.x += prevw;
    d.y += a2.x; d.z += a2.y; d.w += a2.z;

    d = f4add(d, ld4(bias, lane * 4));
    st4(out, idx, d);
}

extern "C" void kernel_launch(void* const* d_in, const int* in_sizes, int n_in,
                              void* d_out, int out_size) {
    const float* x   = (const float*)d_in[0];   // (8, 2048, 128)
    const float* lam = (const float*)d_in[1];   // (1, 1)
    const float* b   = (const float*)d_in[2];   // (1, 1, 128)
    float* out = (float*)d_out;

    const int vblocks = (NN / 4 + NTHREADS - 1) / NTHREADS;   // 2048
    const int fblocks = TT / TTILE;                           // 1024

    k_first<<<vblocks, NTHREADS>>>(x, lam);

    for (int it = 0; it < NFUSED; ++it) {
        if ((it & 1) == 0)
            k_fused<true><<<fblocks, NTHREADS>>>(x, lam);   // A -> B
        else
            k_fused<false><<<fblocks, NTHREADS>>>(x, lam);  // B -> A
    }

    k_final<<<vblocks, NTHREADS>>>(x, b, out);
}